// round 7
// baseline (speedup 1.0000x reference)
#include <cuda_runtime.h>

// ---------------------------------------------------------------------------
// ContrastiveEnergyLearning — fused fp32 MLP energy + InfoNCE stats
// R4: conflict-free float4-interleaved n-mapping (kills 4-way LDS bank
//     conflicts that were the real R2/R3 bottleneck) + packed fma.rn.f32x2
//
// Inputs (metadata order):
//  0 anchor    (B,256) f32      5 W2 (128,256)   6 b2 (128)
//  1 positive  (B,256) f32      7 W3 (64,128)    8 b3 (64)
//  2 negatives (B,16,256) f32   9 W4 (1,64)     10 b4 (1)
//  3 W1 (256,512)  4 b1 (256)
// Output: float[4] = {loss, pos_energy, neg_energy, accuracy}
// ---------------------------------------------------------------------------

#define D     256
#define H1    256
#define H2    128
#define H3    64
#define BMAX  32768
#define NNEG  16
#define CAND  17
#define TEMP_INV (1.0f / 0.07f)

#define BM   64     // pairs per block
#define TPB  256
#define PAD  260    // activation buffer row stride (floats)
#define KT   32     // K-chunk for weight staging

typedef unsigned long long u64t;

// Scratch (static device allocations — no cudaMalloc anywhere)
__device__ float g_A[BMAX * H1];       // anchor-part preactivations (incl. b1)
__device__ float g_W1xT[D * H1];       // W1[:, :256]^T   [k][j]
__device__ float g_W1yT[D * H1];       // W1[:, 256:]^T   [k][j]
__device__ float g_W2T[H1 * H2];       // W2^T            [k][j]
__device__ float g_W3T[H2 * H3];       // W3^T            [k][j]
__device__ float g_E[BMAX * CAND];     // energies
__device__ float g_row[4 * BMAX];      // per-row stats (SoA)

__device__ __forceinline__ float gelu_exact(float x) {
    return 0.5f * x * (1.0f + erff(x * 0.70710678118654752f));
}

// packed f32x2 helpers --------------------------------------------------------
__device__ __forceinline__ u64t pack_dup(float x) {
    u64t r; unsigned u = __float_as_uint(x);
    asm("mov.b64 %0, {%1, %1};" : "=l"(r) : "r"(u));
    return r;
}
__device__ __forceinline__ void unpack2(u64t p, float& lo, float& hi) {
    unsigned a, b;
    asm("mov.b64 {%0, %1}, %2;" : "=r"(a), "=r"(b) : "l"(p));
    lo = __uint_as_float(a); hi = __uint_as_float(b);
}
#define FFMA2(d, a, b) \
    asm("fma.rn.f32x2 %0, %1, %2, %0;" : "+l"(d) : "l"(a), "l"(b))

// Register-blocked tile GEMM with packed f32x2 accumulation.
// Column ownership (conflict-free): thread tx owns cols {64*v + 4*tx + c},
// v in [0, N/64), c in [0,4). Lane stride 16B -> LDS.128 banks 4*tx mod 32
// all distinct per phase -> zero bank conflicts.
// acc layout: acc[mm*NF + v*4 + c] holds column (64*v + 4*tx + c), row ty*4+mm.
template <int N, int K>
__device__ __forceinline__ void gemm_tile(const float* __restrict__ buf,
                                          float* __restrict__ sW,
                                          const float* __restrict__ wT,
                                          float* __restrict__ acc) {
    constexpr int NG = N / 64;   // float4 column groups per thread
    constexpr int NF = 4 * NG;   // floats per thread along n
    constexpr int NP = 2 * NG;   // packed f32x2 pairs per thread along n
    const int tid = threadIdx.x;
    const int tx = tid & 15;
    const int ty = tid >> 4;

    u64t accp[4 * NP];
#pragma unroll
    for (int i = 0; i < 4 * NP; ++i) accp[i] = 0ull;

    for (int k0 = 0; k0 < K; k0 += KT) {
        __syncthreads();  // prior sW reads / buf writes complete
        const float4* src = reinterpret_cast<const float4*>(wT + k0 * N);
#pragma unroll
        for (int i = tid; i < KT * N / 4; i += TPB)
            reinterpret_cast<float4*>(sW)[i] = __ldg(src + i);
        __syncthreads();
#pragma unroll
        for (int kk4 = 0; kk4 < KT; kk4 += 4) {
            float4 a4[4];
#pragma unroll
            for (int mm = 0; mm < 4; ++mm)
                a4[mm] = *reinterpret_cast<const float4*>(
                    &buf[(ty * 4 + mm) * PAD + k0 + kk4]);
#pragma unroll
            for (int u = 0; u < 4; ++u) {
                u64t b2[NP];
#pragma unroll
                for (int v = 0; v < NG; ++v) {
                    // conflict-free: lane stride = 16B
                    float4 t = *reinterpret_cast<const float4*>(
                        &sW[(kk4 + u) * N + v * 64 + 4 * tx]);
                    u64t lo, hi;
                    asm("mov.b64 %0, {%1, %2};" : "=l"(lo)
                        : "r"(__float_as_uint(t.x)), "r"(__float_as_uint(t.y)));
                    asm("mov.b64 %0, {%1, %2};" : "=l"(hi)
                        : "r"(__float_as_uint(t.z)), "r"(__float_as_uint(t.w)));
                    b2[2 * v]     = lo;
                    b2[2 * v + 1] = hi;
                }
#pragma unroll
                for (int mm = 0; mm < 4; ++mm) {
                    const u64t a2 =
                        pack_dup(reinterpret_cast<const float*>(&a4[mm])[u]);
#pragma unroll
                    for (int p = 0; p < NP; ++p)
                        FFMA2(accp[mm * NP + p], a2, b2[p]);
                }
            }
        }
    }
    __syncthreads();  // all buf reads done; caller may overwrite buf
#pragma unroll
    for (int mm = 0; mm < 4; ++mm)
#pragma unroll
        for (int p = 0; p < NP; ++p)
            unpack2(accp[mm * NP + p],
                    acc[mm * NF + 2 * p], acc[mm * NF + 2 * p + 1]);
}

// ---- kernel 0: weight transposes (coalesced writes) ------------------------
__global__ void prep_weights(const float* __restrict__ W1,
                             const float* __restrict__ W2,
                             const float* __restrict__ W3) {
    int i = blockIdx.x * blockDim.x + threadIdx.x;
    if (i < D * H1) {
        int k = i >> 8, j = i & 255;
        g_W1xT[i] = W1[j * 512 + k];
        g_W1yT[i] = W1[j * 512 + 256 + k];
    }
    if (i < H1 * H2) {
        int k = i >> 7, j = i & 127;
        g_W2T[i] = W2[j * 256 + k];
    }
    if (i < H2 * H3) {
        int k = i >> 6, j = i & 63;
        g_W3T[i] = W3[j * 128 + k];
    }
}

// ---- kernel 1: A = anchor @ W1x^T + b1  ------------------------------------
__global__ __launch_bounds__(TPB, 2) void anchor_kernel(
    const float* __restrict__ anchor, const float* __restrict__ b1, int B) {
    extern __shared__ float smem[];
    float* buf = smem;
    float* sW  = smem + BM * PAD;
    const int tid = threadIdx.x;
    const int r0 = blockIdx.x * BM;

    for (int i = tid; i < BM * (D / 4); i += TPB) {
        int m = i >> 6, q = i & 63;
        int r = r0 + m; if (r >= B) r = B - 1;
        *reinterpret_cast<float4*>(&buf[m * PAD + q * 4]) =
            __ldg(reinterpret_cast<const float4*>(anchor + (size_t)r * D) + q);
    }

    constexpr int NG = H1 / 64;
    constexpr int NF = 4 * NG;
    float acc[4 * NF];
    gemm_tile<H1, D>(buf, sW, g_W1xT, acc);

    const int tx = tid & 15, ty = tid >> 4;
#pragma unroll
    for (int mm = 0; mm < 4; ++mm) {
        int r = r0 + ty * 4 + mm;
        if (r < B) {
#pragma unroll
            for (int v = 0; v < NG; ++v) {
                int j = v * 64 + 4 * tx;
                float4 bb = __ldg(reinterpret_cast<const float4*>(b1 + j));
                float4 o;
                o.x = acc[mm * NF + 4 * v + 0] + bb.x;
                o.y = acc[mm * NF + 4 * v + 1] + bb.y;
                o.z = acc[mm * NF + 4 * v + 2] + bb.z;
                o.w = acc[mm * NF + 4 * v + 3] + bb.w;
                *reinterpret_cast<float4*>(&g_A[(size_t)r * H1 + j]) = o;
            }
        }
    }
}

// ---- kernel 2: fused 4-layer MLP per 64-pair tile --------------------------
__global__ __launch_bounds__(TPB, 2) void mlp_kernel(
    const float* __restrict__ positive, const float* __restrict__ negatives,
    const float* __restrict__ b2, const float* __restrict__ b3,
    const float* __restrict__ W4, const float* __restrict__ b4, int B) {
    extern __shared__ float smem[];
    float* buf = smem;              // [BM][PAD] activation buffer (reused)
    float* sW  = smem + BM * PAD;   // [KT][256] weight staging
    const int tid = threadIdx.x;
    const int tx = tid & 15, ty = tid >> 4;
    const int P = B * CAND;
    const int p0 = blockIdx.x * BM;

    // Load Y tile (positive for c==0, negatives otherwise)
    for (int i = tid; i < BM * (D / 4); i += TPB) {
        int m = i >> 6, q = i & 63;
        int p = p0 + m; if (p >= P) p = P - 1;
        int r = p / CAND, c = p - r * CAND;
        const float* y = (c == 0) ? (positive + (size_t)r * D)
                                  : (negatives + ((size_t)r * NNEG + (c - 1)) * D);
        *reinterpret_cast<float4*>(&buf[m * PAD + q * 4]) =
            __ldg(reinterpret_cast<const float4*>(y) + q);
    }

    {   // layer 1: h1 = gelu(Y @ W1y^T + A[row])
        constexpr int NG = H1 / 64;
        constexpr int NF = 4 * NG;
        float acc[4 * NF];
        gemm_tile<H1, D>(buf, sW, g_W1yT, acc);
#pragma unroll
        for (int mm = 0; mm < 4; ++mm) {
            int m = ty * 4 + mm;
            int p = p0 + m; if (p >= P) p = P - 1;
            int r = p / CAND;
#pragma unroll
            for (int v = 0; v < NG; ++v) {
                int j = v * 64 + 4 * tx;
                float4 av = __ldg(reinterpret_cast<const float4*>(&g_A[(size_t)r * H1 + j]));
                buf[m * PAD + j + 0] = gelu_exact(acc[mm * NF + 4 * v + 0] + av.x);
                buf[m * PAD + j + 1] = gelu_exact(acc[mm * NF + 4 * v + 1] + av.y);
                buf[m * PAD + j + 2] = gelu_exact(acc[mm * NF + 4 * v + 2] + av.z);
                buf[m * PAD + j + 3] = gelu_exact(acc[mm * NF + 4 * v + 3] + av.w);
            }
        }
    }
    {   // layer 2: h2 = gelu(h1 @ W2^T + b2)
        constexpr int NG = H2 / 64;
        constexpr int NF = 4 * NG;
        float acc[4 * NF];
        gemm_tile<H2, H1>(buf, sW, g_W2T, acc);
#pragma unroll
        for (int mm = 0; mm < 4; ++mm) {
            int m = ty * 4 + mm;
#pragma unroll
            for (int v = 0; v < NG; ++v) {
                int j = v * 64 + 4 * tx;
                float4 bb = __ldg(reinterpret_cast<const float4*>(b2 + j));
                buf[m * PAD + j + 0] = gelu_exact(acc[mm * NF + 4 * v + 0] + bb.x);
                buf[m * PAD + j + 1] = gelu_exact(acc[mm * NF + 4 * v + 1] + bb.y);
                buf[m * PAD + j + 2] = gelu_exact(acc[mm * NF + 4 * v + 2] + bb.z);
                buf[m * PAD + j + 3] = gelu_exact(acc[mm * NF + 4 * v + 3] + bb.w);
            }
        }
    }
    {   // layer 3: h3 = gelu(h2 @ W3^T + b3)
        constexpr int NG = H3 / 64;
        constexpr int NF = 4 * NG;
        float acc[4 * NF];
        gemm_tile<H3, H2>(buf, sW, g_W3T, acc);
#pragma unroll
        for (int mm = 0; mm < 4; ++mm) {
            int m = ty * 4 + mm;
#pragma unroll
            for (int v = 0; v < NG; ++v) {
                int j = v * 64 + 4 * tx;
                float4 bb = __ldg(reinterpret_cast<const float4*>(b3 + j));
                buf[m * PAD + j + 0] = gelu_exact(acc[mm * NF + 4 * v + 0] + bb.x);
                buf[m * PAD + j + 1] = gelu_exact(acc[mm * NF + 4 * v + 1] + bb.y);
                buf[m * PAD + j + 2] = gelu_exact(acc[mm * NF + 4 * v + 2] + bb.z);
                buf[m * PAD + j + 3] = gelu_exact(acc[mm * NF + 4 * v + 3] + bb.w);
            }
        }
    }
    // layer 4: e = h3 . W4 + b4 (one thread per pair)
    __syncthreads();
    if (tid < BM) {
        int p = p0 + tid;
        if (p < P) {
            float s = __ldg(b4);
#pragma unroll
            for (int k = 0; k < H3; ++k)
                s = fmaf(__ldg(W4 + k), buf[tid * PAD + k], s);
            g_E[p] = s;
        }
    }
}

// ---- kernel 3: per-row softmax/loss/argmin stats ---------------------------
__global__ void rowstats_kernel(int B) {
    int r = blockIdx.x * blockDim.x + threadIdx.x;
    if (r >= B) return;
    float e[CAND];
#pragma unroll
    for (int i = 0; i < CAND; ++i) e[i] = g_E[r * CAND + i];

    float l0 = -e[0] * TEMP_INV;
    float mx = l0;
#pragma unroll
    for (int i = 1; i < CAND; ++i) mx = fmaxf(mx, -e[i] * TEMP_INV);
    float s = 0.0f;
#pragma unroll
    for (int i = 0; i < CAND; ++i) s += expf(-e[i] * TEMP_INV - mx);
    float lse = mx + logf(s);

    float negs = 0.0f;
#pragma unroll
    for (int i = 1; i < CAND; ++i) negs += e[i];

    int am = 0; float best = e[0];
#pragma unroll
    for (int i = 1; i < CAND; ++i)
        if (e[i] < best) { best = e[i]; am = i; }

    g_row[0 * BMAX + r] = lse - l0;
    g_row[1 * BMAX + r] = e[0];
    g_row[2 * BMAX + r] = negs;
    g_row[3 * BMAX + r] = (am == 0) ? 1.0f : 0.0f;
}

// ---- kernel 4: deterministic single-block reduction ------------------------
__global__ void reduce_kernel(float* __restrict__ out, int B) {
    __shared__ float sred[1024];
    const int tid = threadIdx.x;
    float totals[4];
    for (int v = 0; v < 4; ++v) {
        float s = 0.0f;
        for (int i = tid; i < B; i += 1024) s += g_row[v * BMAX + i];
        sred[tid] = s;
        __syncthreads();
        for (int off = 512; off > 0; off >>= 1) {
            if (tid < off) sred[tid] += sred[tid + off];
            __syncthreads();
        }
        totals[v] = sred[0];
        __syncthreads();
    }
    if (tid == 0) {
        const float fB = (float)B;
        out[0] = totals[0] / fB;             // loss
        out[1] = totals[1] / fB;             // pos_energy
        out[2] = totals[2] / (fB * NNEG);    // neg_energy
        out[3] = totals[3] / fB;             // accuracy
    }
}

// ---------------------------------------------------------------------------
extern "C" void kernel_launch(void* const* d_in, const int* in_sizes, int n_in,
                              void* d_out, int out_size) {
    const float* anchor    = (const float*)d_in[0];
    const float* positive  = (const float*)d_in[1];
    const float* negatives = (const float*)d_in[2];
    const float* W1        = (const float*)d_in[3];
    const float* b1        = (const float*)d_in[4];
    const float* W2        = (const float*)d_in[5];
    const float* b2        = (const float*)d_in[6];
    const float* W3        = (const float*)d_in[7];
    const float* b3        = (const float*)d_in[8];
    const float* W4        = (const float*)d_in[9];
    const float* b4        = (const float*)d_in[10];
    float* out = (float*)d_out;

    int B = in_sizes[0] / D;
    if (B > BMAX) B = BMAX;
    const int P = B * CAND;

    const int smem = (BM * PAD + KT * 256) * (int)sizeof(float);  // 99328 B
    cudaFuncSetAttribute(anchor_kernel, cudaFuncAttributeMaxDynamicSharedMemorySize, smem);
    cudaFuncSetAttribute(mlp_kernel,    cudaFuncAttributeMaxDynamicSharedMemorySize, smem);

    prep_weights<<<(D * H1 + 255) / 256, 256>>>(W1, W2, W3);
    anchor_kernel<<<(B + BM - 1) / BM, TPB, smem>>>(anchor, b1, B);
    mlp_kernel<<<(P + BM - 1) / BM, TPB, smem>>>(positive, negatives, b2, b3, W4, b4, B);
    rowstats_kernel<<<(B + 255) / 256, 256>>>(B);
    reduce_kernel<<<1, 1024>>>(out, B);
}

// round 8
// speedup vs baseline: 1.0016x; 1.0016x over previous
#include <cuda_runtime.h>

// ---------------------------------------------------------------------------
// ContrastiveEnergyLearning — fused fp32 MLP energy + InfoNCE stats
// R4: conflict-free float4-interleaved n-mapping (kills 4-way LDS bank
//     conflicts that were the real R2/R3 bottleneck) + packed fma.rn.f32x2
//
// Inputs (metadata order):
//  0 anchor    (B,256) f32      5 W2 (128,256)   6 b2 (128)
//  1 positive  (B,256) f32      7 W3 (64,128)    8 b3 (64)
//  2 negatives (B,16,256) f32   9 W4 (1,64)     10 b4 (1)
//  3 W1 (256,512)  4 b1 (256)
// Output: float[4] = {loss, pos_energy, neg_energy, accuracy}
// ---------------------------------------------------------------------------

#define D     256
#define H1    256
#define H2    128
#define H3    64
#define BMAX  32768
#define NNEG  16
#define CAND  17
#define TEMP_INV (1.0f / 0.07f)

#define BM   64     // pairs per block
#define TPB  256
#define PAD  260    // activation buffer row stride (floats)
#define KT   32     // K-chunk for weight staging

typedef unsigned long long u64t;

// Scratch (static device allocations — no cudaMalloc anywhere)
__device__ float g_A[BMAX * H1];       // anchor-part preactivations (incl. b1)
__device__ float g_W1xT[D * H1];       // W1[:, :256]^T   [k][j]
__device__ float g_W1yT[D * H1];       // W1[:, 256:]^T   [k][j]
__device__ float g_W2T[H1 * H2];       // W2^T            [k][j]
__device__ float g_W3T[H2 * H3];       // W3^T            [k][j]
__device__ float g_E[BMAX * CAND];     // energies
__device__ float g_row[4 * BMAX];      // per-row stats (SoA)

__device__ __forceinline__ float gelu_exact(float x) {
    return 0.5f * x * (1.0f + erff(x * 0.70710678118654752f));
}

// packed f32x2 helpers --------------------------------------------------------
__device__ __forceinline__ u64t pack_dup(float x) {
    u64t r; unsigned u = __float_as_uint(x);
    asm("mov.b64 %0, {%1, %1};" : "=l"(r) : "r"(u));
    return r;
}
__device__ __forceinline__ void unpack2(u64t p, float& lo, float& hi) {
    unsigned a, b;
    asm("mov.b64 {%0, %1}, %2;" : "=r"(a), "=r"(b) : "l"(p));
    lo = __uint_as_float(a); hi = __uint_as_float(b);
}
#define FFMA2(d, a, b) \
    asm("fma.rn.f32x2 %0, %1, %2, %0;" : "+l"(d) : "l"(a), "l"(b))

// Register-blocked tile GEMM with packed f32x2 accumulation.
// Column ownership (conflict-free): thread tx owns cols {64*v + 4*tx + c},
// v in [0, N/64), c in [0,4). Lane stride 16B -> LDS.128 banks 4*tx mod 32
// all distinct per phase -> zero bank conflicts.
// acc layout: acc[mm*NF + v*4 + c] holds column (64*v + 4*tx + c), row ty*4+mm.
template <int N, int K>
__device__ __forceinline__ void gemm_tile(const float* __restrict__ buf,
                                          float* __restrict__ sW,
                                          const float* __restrict__ wT,
                                          float* __restrict__ acc) {
    constexpr int NG = N / 64;   // float4 column groups per thread
    constexpr int NF = 4 * NG;   // floats per thread along n
    constexpr int NP = 2 * NG;   // packed f32x2 pairs per thread along n
    const int tid = threadIdx.x;
    const int tx = tid & 15;
    const int ty = tid >> 4;

    u64t accp[4 * NP];
#pragma unroll
    for (int i = 0; i < 4 * NP; ++i) accp[i] = 0ull;

    for (int k0 = 0; k0 < K; k0 += KT) {
        __syncthreads();  // prior sW reads / buf writes complete
        const float4* src = reinterpret_cast<const float4*>(wT + k0 * N);
#pragma unroll
        for (int i = tid; i < KT * N / 4; i += TPB)
            reinterpret_cast<float4*>(sW)[i] = __ldg(src + i);
        __syncthreads();
#pragma unroll
        for (int kk4 = 0; kk4 < KT; kk4 += 4) {
            float4 a4[4];
#pragma unroll
            for (int mm = 0; mm < 4; ++mm)
                a4[mm] = *reinterpret_cast<const float4*>(
                    &buf[(ty * 4 + mm) * PAD + k0 + kk4]);
#pragma unroll
            for (int u = 0; u < 4; ++u) {
                u64t b2[NP];
#pragma unroll
                for (int v = 0; v < NG; ++v) {
                    // conflict-free: lane stride = 16B
                    float4 t = *reinterpret_cast<const float4*>(
                        &sW[(kk4 + u) * N + v * 64 + 4 * tx]);
                    u64t lo, hi;
                    asm("mov.b64 %0, {%1, %2};" : "=l"(lo)
                        : "r"(__float_as_uint(t.x)), "r"(__float_as_uint(t.y)));
                    asm("mov.b64 %0, {%1, %2};" : "=l"(hi)
                        : "r"(__float_as_uint(t.z)), "r"(__float_as_uint(t.w)));
                    b2[2 * v]     = lo;
                    b2[2 * v + 1] = hi;
                }
#pragma unroll
                for (int mm = 0; mm < 4; ++mm) {
                    const u64t a2 =
                        pack_dup(reinterpret_cast<const float*>(&a4[mm])[u]);
#pragma unroll
                    for (int p = 0; p < NP; ++p)
                        FFMA2(accp[mm * NP + p], a2, b2[p]);
                }
            }
        }
    }
    __syncthreads();  // all buf reads done; caller may overwrite buf
#pragma unroll
    for (int mm = 0; mm < 4; ++mm)
#pragma unroll
        for (int p = 0; p < NP; ++p)
            unpack2(accp[mm * NP + p],
                    acc[mm * NF + 2 * p], acc[mm * NF + 2 * p + 1]);
}

// ---- kernel 0: weight transposes (coalesced writes) ------------------------
__global__ void prep_weights(const float* __restrict__ W1,
                             const float* __restrict__ W2,
                             const float* __restrict__ W3) {
    int i = blockIdx.x * blockDim.x + threadIdx.x;
    if (i < D * H1) {
        int k = i >> 8, j = i & 255;
        g_W1xT[i] = W1[j * 512 + k];
        g_W1yT[i] = W1[j * 512 + 256 + k];
    }
    if (i < H1 * H2) {
        int k = i >> 7, j = i & 127;
        g_W2T[i] = W2[j * 256 + k];
    }
    if (i < H2 * H3) {
        int k = i >> 6, j = i & 63;
        g_W3T[i] = W3[j * 128 + k];
    }
}

// ---- kernel 1: A = anchor @ W1x^T + b1  ------------------------------------
__global__ __launch_bounds__(TPB, 2) void anchor_kernel(
    const float* __restrict__ anchor, const float* __restrict__ b1, int B) {
    extern __shared__ float smem[];
    float* buf = smem;
    float* sW  = smem + BM * PAD;
    const int tid = threadIdx.x;
    const int r0 = blockIdx.x * BM;

    for (int i = tid; i < BM * (D / 4); i += TPB) {
        int m = i >> 6, q = i & 63;
        int r = r0 + m; if (r >= B) r = B - 1;
        *reinterpret_cast<float4*>(&buf[m * PAD + q * 4]) =
            __ldg(reinterpret_cast<const float4*>(anchor + (size_t)r * D) + q);
    }

    constexpr int NG = H1 / 64;
    constexpr int NF = 4 * NG;
    float acc[4 * NF];
    gemm_tile<H1, D>(buf, sW, g_W1xT, acc);

    const int tx = tid & 15, ty = tid >> 4;
#pragma unroll
    for (int mm = 0; mm < 4; ++mm) {
        int r = r0 + ty * 4 + mm;
        if (r < B) {
#pragma unroll
            for (int v = 0; v < NG; ++v) {
                int j = v * 64 + 4 * tx;
                float4 bb = __ldg(reinterpret_cast<const float4*>(b1 + j));
                float4 o;
                o.x = acc[mm * NF + 4 * v + 0] + bb.x;
                o.y = acc[mm * NF + 4 * v + 1] + bb.y;
                o.z = acc[mm * NF + 4 * v + 2] + bb.z;
                o.w = acc[mm * NF + 4 * v + 3] + bb.w;
                *reinterpret_cast<float4*>(&g_A[(size_t)r * H1 + j]) = o;
            }
        }
    }
}

// ---- kernel 2: fused 4-layer MLP per 64-pair tile --------------------------
__global__ __launch_bounds__(TPB, 2) void mlp_kernel(
    const float* __restrict__ positive, const float* __restrict__ negatives,
    const float* __restrict__ b2, const float* __restrict__ b3,
    const float* __restrict__ W4, const float* __restrict__ b4, int B) {
    extern __shared__ float smem[];
    float* buf = smem;              // [BM][PAD] activation buffer (reused)
    float* sW  = smem + BM * PAD;   // [KT][256] weight staging
    const int tid = threadIdx.x;
    const int tx = tid & 15, ty = tid >> 4;
    const int P = B * CAND;
    const int p0 = blockIdx.x * BM;

    // Load Y tile (positive for c==0, negatives otherwise)
    for (int i = tid; i < BM * (D / 4); i += TPB) {
        int m = i >> 6, q = i & 63;
        int p = p0 + m; if (p >= P) p = P - 1;
        int r = p / CAND, c = p - r * CAND;
        const float* y = (c == 0) ? (positive + (size_t)r * D)
                                  : (negatives + ((size_t)r * NNEG + (c - 1)) * D);
        *reinterpret_cast<float4*>(&buf[m * PAD + q * 4]) =
            __ldg(reinterpret_cast<const float4*>(y) + q);
    }

    {   // layer 1: h1 = gelu(Y @ W1y^T + A[row])
        constexpr int NG = H1 / 64;
        constexpr int NF = 4 * NG;
        float acc[4 * NF];
        gemm_tile<H1, D>(buf, sW, g_W1yT, acc);
#pragma unroll
        for (int mm = 0; mm < 4; ++mm) {
            int m = ty * 4 + mm;
            int p = p0 + m; if (p >= P) p = P - 1;
            int r = p / CAND;
#pragma unroll
            for (int v = 0; v < NG; ++v) {
                int j = v * 64 + 4 * tx;
                float4 av = __ldg(reinterpret_cast<const float4*>(&g_A[(size_t)r * H1 + j]));
                buf[m * PAD + j + 0] = gelu_exact(acc[mm * NF + 4 * v + 0] + av.x);
                buf[m * PAD + j + 1] = gelu_exact(acc[mm * NF + 4 * v + 1] + av.y);
                buf[m * PAD + j + 2] = gelu_exact(acc[mm * NF + 4 * v + 2] + av.z);
                buf[m * PAD + j + 3] = gelu_exact(acc[mm * NF + 4 * v + 3] + av.w);
            }
        }
    }
    {   // layer 2: h2 = gelu(h1 @ W2^T + b2)
        constexpr int NG = H2 / 64;
        constexpr int NF = 4 * NG;
        float acc[4 * NF];
        gemm_tile<H2, H1>(buf, sW, g_W2T, acc);
#pragma unroll
        for (int mm = 0; mm < 4; ++mm) {
            int m = ty * 4 + mm;
#pragma unroll
            for (int v = 0; v < NG; ++v) {
                int j = v * 64 + 4 * tx;
                float4 bb = __ldg(reinterpret_cast<const float4*>(b2 + j));
                buf[m * PAD + j + 0] = gelu_exact(acc[mm * NF + 4 * v + 0] + bb.x);
                buf[m * PAD + j + 1] = gelu_exact(acc[mm * NF + 4 * v + 1] + bb.y);
                buf[m * PAD + j + 2] = gelu_exact(acc[mm * NF + 4 * v + 2] + bb.z);
                buf[m * PAD + j + 3] = gelu_exact(acc[mm * NF + 4 * v + 3] + bb.w);
            }
        }
    }
    {   // layer 3: h3 = gelu(h2 @ W3^T + b3)
        constexpr int NG = H3 / 64;
        constexpr int NF = 4 * NG;
        float acc[4 * NF];
        gemm_tile<H3, H2>(buf, sW, g_W3T, acc);
#pragma unroll
        for (int mm = 0; mm < 4; ++mm) {
            int m = ty * 4 + mm;
#pragma unroll
            for (int v = 0; v < NG; ++v) {
                int j = v * 64 + 4 * tx;
                float4 bb = __ldg(reinterpret_cast<const float4*>(b3 + j));
                buf[m * PAD + j + 0] = gelu_exact(acc[mm * NF + 4 * v + 0] + bb.x);
                buf[m * PAD + j + 1] = gelu_exact(acc[mm * NF + 4 * v + 1] + bb.y);
                buf[m * PAD + j + 2] = gelu_exact(acc[mm * NF + 4 * v + 2] + bb.z);
                buf[m * PAD + j + 3] = gelu_exact(acc[mm * NF + 4 * v + 3] + bb.w);
            }
        }
    }
    // layer 4: e = h3 . W4 + b4 (one thread per pair)
    __syncthreads();
    if (tid < BM) {
        int p = p0 + tid;
        if (p < P) {
            float s = __ldg(b4);
#pragma unroll
            for (int k = 0; k < H3; ++k)
                s = fmaf(__ldg(W4 + k), buf[tid * PAD + k], s);
            g_E[p] = s;
        }
    }
}

// ---- kernel 3: per-row softmax/loss/argmin stats ---------------------------
__global__ void rowstats_kernel(int B) {
    int r = blockIdx.x * blockDim.x + threadIdx.x;
    if (r >= B) return;
    float e[CAND];
#pragma unroll
    for (int i = 0; i < CAND; ++i) e[i] = g_E[r * CAND + i];

    float l0 = -e[0] * TEMP_INV;
    float mx = l0;
#pragma unroll
    for (int i = 1; i < CAND; ++i) mx = fmaxf(mx, -e[i] * TEMP_INV);
    float s = 0.0f;
#pragma unroll
    for (int i = 0; i < CAND; ++i) s += expf(-e[i] * TEMP_INV - mx);
    float lse = mx + logf(s);

    float negs = 0.0f;
#pragma unroll
    for (int i = 1; i < CAND; ++i) negs += e[i];

    int am = 0; float best = e[0];
#pragma unroll
    for (int i = 1; i < CAND; ++i)
        if (e[i] < best) { best = e[i]; am = i; }

    g_row[0 * BMAX + r] = lse - l0;
    g_row[1 * BMAX + r] = e[0];
    g_row[2 * BMAX + r] = negs;
    g_row[3 * BMAX + r] = (am == 0) ? 1.0f : 0.0f;
}

// ---- kernel 4: deterministic single-block reduction ------------------------
__global__ void reduce_kernel(float* __restrict__ out, int B) {
    __shared__ float sred[1024];
    const int tid = threadIdx.x;
    float totals[4];
    for (int v = 0; v < 4; ++v) {
        float s = 0.0f;
        for (int i = tid; i < B; i += 1024) s += g_row[v * BMAX + i];
        sred[tid] = s;
        __syncthreads();
        for (int off = 512; off > 0; off >>= 1) {
            if (tid < off) sred[tid] += sred[tid + off];
            __syncthreads();
        }
        totals[v] = sred[0];
        __syncthreads();
    }
    if (tid == 0) {
        const float fB = (float)B;
        out[0] = totals[0] / fB;             // loss
        out[1] = totals[1] / fB;             // pos_energy
        out[2] = totals[2] / (fB * NNEG);    // neg_energy
        out[3] = totals[3] / fB;             // accuracy
    }
}

// ---------------------------------------------------------------------------
extern "C" void kernel_launch(void* const* d_in, const int* in_sizes, int n_in,
                              void* d_out, int out_size) {
    const float* anchor    = (const float*)d_in[0];
    const float* positive  = (const float*)d_in[1];
    const float* negatives = (const float*)d_in[2];
    const float* W1        = (const float*)d_in[3];
    const float* b1        = (const float*)d_in[4];
    const float* W2        = (const float*)d_in[5];
    const float* b2        = (const float*)d_in[6];
    const float* W3        = (const float*)d_in[7];
    const float* b3        = (const float*)d_in[8];
    const float* W4        = (const float*)d_in[9];
    const float* b4        = (const float*)d_in[10];
    float* out = (float*)d_out;

    int B = in_sizes[0] / D;
    if (B > BMAX) B = BMAX;
    const int P = B * CAND;

    const int smem = (BM * PAD + KT * 256) * (int)sizeof(float);  // 99328 B
    cudaFuncSetAttribute(anchor_kernel, cudaFuncAttributeMaxDynamicSharedMemorySize, smem);
    cudaFuncSetAttribute(mlp_kernel,    cudaFuncAttributeMaxDynamicSharedMemorySize, smem);

    prep_weights<<<(D * H1 + 255) / 256, 256>>>(W1, W2, W3);
    anchor_kernel<<<(B + BM - 1) / BM, TPB, smem>>>(anchor, b1, B);
    mlp_kernel<<<(P + BM - 1) / BM, TPB, smem>>>(positive, negatives, b2, b3, W4, b4, B);
    rowstats_kernel<<<(B + 255) / 256, 256>>>(B);
    reduce_kernel<<<1, 1024>>>(out, B);
}